// round 1
// baseline (speedup 1.0000x reference)
#include <cuda_runtime.h>
#include <math.h>
#include <stdint.h>

// Problem constants
#define B_   8
#define T_   2048
#define DIM_ 512
#define NH_  8
#define NKV_ 4
#define HD_  64
#define EPS_ 1.1920928955078125e-07f
// log2(10000)/32
#define FREQ_C 0.41524101186091903f

// ---------------- scratch (device globals; no allocation allowed) ----------
__device__ float g_qkv[(size_t)B_ * T_ * 1024];        // raw q|k|v projections
__device__ float g_q[(size_t)B_ * NH_ * T_ * HD_];     // [b][h][t][d]
__device__ float g_k[(size_t)B_ * NKV_ * T_ * HD_];
__device__ float g_v[(size_t)B_ * NKV_ * T_ * HD_];
__device__ float g_y[(size_t)B_ * T_ * DIM_];          // attention output

// ---------------- GEMM: C[M][N] = A[M][512] @ W[N][512]^T ------------------
// grid (M/128, N/128), 256 threads, 8x8 register tile
#define GBM 128
#define GBN 128
#define GBK 32

__global__ __launch_bounds__(256) void gemm_kernel(
    const float* __restrict__ A, const float* __restrict__ W,
    float* __restrict__ C, int ldc, int coff)
{
    __shared__ float Xs[GBK][GBM + 4];
    __shared__ float Ws[GBK][GBN + 4];

    const int m0 = blockIdx.x * GBM;
    const int n0 = blockIdx.y * GBN;
    const int tid = threadIdx.x;
    const int tm = (tid >> 4) << 3;   // 0..120
    const int tn = (tid & 15) << 3;   // 0..120

    float acc[8][8];
#pragma unroll
    for (int i = 0; i < 8; i++)
#pragma unroll
        for (int j = 0; j < 8; j++) acc[i][j] = 0.f;

    const int lr = tid >> 3;     // 0..31
    const int lc4 = tid & 7;     // 0..7  (float4 column)

    for (int k0 = 0; k0 < 512; k0 += GBK) {
#pragma unroll
        for (int p = 0; p < 4; p++) {
            int r = lr + p * 32;
            float4 av = *(const float4*)&A[(size_t)(m0 + r) * 512 + k0 + lc4 * 4];
            Xs[lc4 * 4 + 0][r] = av.x;
            Xs[lc4 * 4 + 1][r] = av.y;
            Xs[lc4 * 4 + 2][r] = av.z;
            Xs[lc4 * 4 + 3][r] = av.w;
            float4 wv = *(const float4*)&W[(size_t)(n0 + r) * 512 + k0 + lc4 * 4];
            Ws[lc4 * 4 + 0][r] = wv.x;
            Ws[lc4 * 4 + 1][r] = wv.y;
            Ws[lc4 * 4 + 2][r] = wv.z;
            Ws[lc4 * 4 + 3][r] = wv.w;
        }
        __syncthreads();

#pragma unroll
        for (int k = 0; k < GBK; k++) {
            float4 xa = *(const float4*)&Xs[k][tm];
            float4 xb = *(const float4*)&Xs[k][tm + 4];
            float4 wa = *(const float4*)&Ws[k][tn];
            float4 wb = *(const float4*)&Ws[k][tn + 4];
            float xv[8] = {xa.x, xa.y, xa.z, xa.w, xb.x, xb.y, xb.z, xb.w};
            float wv[8] = {wa.x, wa.y, wa.z, wa.w, wb.x, wb.y, wb.z, wb.w};
#pragma unroll
            for (int i = 0; i < 8; i++)
#pragma unroll
                for (int j = 0; j < 8; j++)
                    acc[i][j] = fmaf(xv[i], wv[j], acc[i][j]);
        }
        __syncthreads();
    }

#pragma unroll
    for (int i = 0; i < 8; i++) {
        float* cp = C + (size_t)(m0 + tm + i) * ldc + coff + n0 + tn;
        float4 c0 = make_float4(acc[i][0], acc[i][1], acc[i][2], acc[i][3]);
        float4 c1 = make_float4(acc[i][4], acc[i][5], acc[i][6], acc[i][7]);
        *(float4*)cp = c0;
        *(float4*)(cp + 4) = c1;
    }
}

// ---------------- RMSNorm + RoPE epilogue ---------------------------------
// one block per token; warp w handles q head w, warps 0..3 also k head w.
__device__ __forceinline__ void norm_rope_head(
    const float* __restrict__ src, float* __restrict__ dst,
    int lane, float cv, float sv)
{
    float x1 = src[lane];
    float x2 = src[lane + 32];
    float ss = x1 * x1 + x2 * x2;
#pragma unroll
    for (int off = 16; off > 0; off >>= 1)
        ss += __shfl_xor_sync(0xffffffffu, ss, off);
    float ir = rsqrtf(ss * (1.f / 64.f) + EPS_);
    x1 *= ir;
    x2 *= ir;
    dst[lane]      = x1 * cv + x2 * sv;
    dst[lane + 32] = x2 * cv - x1 * sv;
}

__global__ __launch_bounds__(256) void rope_kernel()
{
    const int tok = blockIdx.x;
    const int b = tok >> 11;
    const int t = tok & (T_ - 1);
    const int lane = threadIdx.x & 31;
    const int w = threadIdx.x >> 5;

    const float* row = g_qkv + (size_t)tok * 1024;

    float inv_freq = exp2f(-(float)lane * FREQ_C);
    float f = (float)t * inv_freq;
    float sv, cv;
    sincosf(f, &sv, &cv);   // precise version: args up to ~2048

    // q head w
    norm_rope_head(row + w * 64,
                   g_q + (((size_t)b * NH_ + w) * T_ + t) * HD_,
                   lane, cv, sv);
    // k head w (warps 0..3)
    if (w < 4) {
        norm_rope_head(row + 512 + w * 64,
                       g_k + (((size_t)b * NKV_ + w) * T_ + t) * HD_,
                       lane, cv, sv);
    }
    // v copy (each thread one element)
    {
        int i = threadIdx.x;           // 0..255
        int vh = i >> 6, d = i & 63;
        g_v[(((size_t)b * NKV_ + vh) * T_ + t) * HD_ + d] = row[768 + i];
    }
}

// ---------------- causal flash attention ----------------------------------
// grid (T/BM, NH, B), 128 threads, thread-per-query-row, BN=32 kv tiles.
#define ABM 128
#define ABN 32
#define QPAD 68   // Q row stride in smem (float4-aligned, conflict-free)

__global__ __launch_bounds__(128) void attn_kernel()
{
    extern __shared__ float sm[];
    float* Qs = sm;                       // ABM x QPAD
    float* Ks = sm + ABM * QPAD;          // ABN x 64 (broadcast reads; no pad)
    float* Vs = Ks + ABN * HD_;           // ABN x 64

    const int tid = threadIdx.x;
    // heavy q-tiles first (better tail behavior under causal imbalance)
    const int q0 = (gridDim.x - 1 - blockIdx.x) * ABM;
    const int h = blockIdx.y;
    const int b = blockIdx.z;
    const int kvh = h >> 1;               // GQA: rep = 2

    // load Q tile (coalesced float4)
    {
        const float* qb = g_q + (((size_t)b * NH_ + h) * T_ + q0) * HD_;
#pragma unroll
        for (int p = 0; p < 16; p++) {
            int i = tid + p * 128;        // 0..2047 float4 index
            int row = i >> 4, c4 = i & 15;
            *(float4*)(Qs + row * QPAD + c4 * 4) =
                ((const float4*)qb)[i];
        }
    }
    __syncthreads();

    const int r = tid;                    // query row within tile
    const int gi = q0 + r;                // global query index
    float m = -INFINITY, l = 0.f;
    float O[HD_];
#pragma unroll
    for (int d = 0; d < HD_; d++) O[d] = 0.f;

    const float* kb0 = g_k + (((size_t)b * NKV_ + kvh) * T_) * HD_;
    const float* vb0 = g_v + (((size_t)b * NKV_ + kvh) * T_) * HD_;

    const int nkt = q0 / ABN + ABM / ABN; // tiles covering j <= q0+127

    for (int kt = 0; kt < nkt; kt++) {
        // load K/V tile (coalesced; 512 float4 each over 128 threads)
        {
            const float4* kp = (const float4*)(kb0 + (size_t)kt * ABN * HD_);
            const float4* vp = (const float4*)(vb0 + (size_t)kt * ABN * HD_);
#pragma unroll
            for (int p = 0; p < 4; p++) {
                int i = tid + p * 128;    // 0..511
                ((float4*)Ks)[i] = kp[i];
                ((float4*)Vs)[i] = vp[i];
            }
        }
        __syncthreads();

        // scores S = Q . K^T
        float S[ABN];
#pragma unroll
        for (int c = 0; c < ABN; c++) S[c] = 0.f;
#pragma unroll 4
        for (int d4 = 0; d4 < 16; d4++) {
            float4 q4 = *(const float4*)(Qs + r * QPAD + d4 * 4);
#pragma unroll
            for (int c = 0; c < ABN; c++) {
                float4 k4 = *(const float4*)(Ks + c * HD_ + d4 * 4);
                S[c] = fmaf(q4.x, k4.x, S[c]);
                S[c] = fmaf(q4.y, k4.y, S[c]);
                S[c] = fmaf(q4.z, k4.z, S[c]);
                S[c] = fmaf(q4.w, k4.w, S[c]);
            }
        }

        // scale + causal mask + online softmax
        const int jb = kt * ABN;
        float tmax = -INFINITY;
#pragma unroll
        for (int c = 0; c < ABN; c++) {
            float sc = S[c] * 0.125f;
            if (jb + c > gi) sc = -INFINITY;
            S[c] = sc;
            tmax = fmaxf(tmax, sc);
        }
        float mnew = fmaxf(m, tmax);
        float corr = __expf(m - mnew);
        float psum = 0.f;
#pragma unroll
        for (int c = 0; c < ABN; c++) {
            float p = __expf(S[c] - mnew);
            S[c] = p;
            psum += p;
        }
        l = l * corr + psum;
        m = mnew;
#pragma unroll
        for (int d = 0; d < HD_; d++) O[d] *= corr;

        // O += P @ V
#pragma unroll
        for (int c = 0; c < ABN; c++) {
            float p = S[c];
#pragma unroll
            for (int d4 = 0; d4 < 16; d4++) {
                float4 v4 = *(const float4*)(Vs + c * HD_ + d4 * 4);
                O[d4 * 4 + 0] = fmaf(p, v4.x, O[d4 * 4 + 0]);
                O[d4 * 4 + 1] = fmaf(p, v4.y, O[d4 * 4 + 1]);
                O[d4 * 4 + 2] = fmaf(p, v4.z, O[d4 * 4 + 2]);
                O[d4 * 4 + 3] = fmaf(p, v4.w, O[d4 * 4 + 3]);
            }
        }
        __syncthreads();
    }

    // normalize and stage into smem for coalesced writeback
    float inv_l = 1.f / l;
#pragma unroll
    for (int d4 = 0; d4 < 16; d4++) {
        float4 o4 = make_float4(O[d4 * 4 + 0] * inv_l, O[d4 * 4 + 1] * inv_l,
                                O[d4 * 4 + 2] * inv_l, O[d4 * 4 + 3] * inv_l);
        *(float4*)(Qs + r * QPAD + d4 * 4) = o4;
    }
    __syncthreads();

    float* yb = g_y + ((size_t)b * T_ + q0) * DIM_ + h * HD_;
#pragma unroll
    for (int p = 0; p < 16; p++) {
        int i = tid + p * 128;
        int row = i >> 4, c4 = i & 15;
        *(float4*)(yb + (size_t)row * DIM_ + c4 * 4) =
            *(const float4*)(Qs + row * QPAD + c4 * 4);
    }
}

// ---------------- launch ---------------------------------------------------
extern "C" void kernel_launch(void* const* d_in, const int* in_sizes, int n_in,
                              void* d_out, int out_size)
{
    const float* x  = (const float*)d_in[0];
    const float* Wq = (const float*)d_in[1];
    const float* Wk = (const float*)d_in[2];
    const float* Wv = (const float*)d_in[3];
    const float* Wp = (const float*)d_in[4];
    float* out = (float*)d_out;

    float* qkv;  cudaGetSymbolAddress((void**)&qkv, g_qkv);
    float* ybuf; cudaGetSymbolAddress((void**)&ybuf, g_y);

    const int M = B_ * T_;  // 16384

    // QKV projections into g_qkv (q|k|v columns)
    gemm_kernel<<<dim3(M / GBM, 512 / GBN), 256>>>(x, Wq, qkv, 1024, 0);
    gemm_kernel<<<dim3(M / GBM, 256 / GBN), 256>>>(x, Wk, qkv, 1024, 512);
    gemm_kernel<<<dim3(M / GBM, 256 / GBN), 256>>>(x, Wv, qkv, 1024, 768);

    // RMSNorm + RoPE + scatter to [b][h][t][d]
    rope_kernel<<<M, 256>>>();

    // attention
    static int smem_set = 0;
    const int attn_smem = (ABM * QPAD + 2 * ABN * HD_) * sizeof(float); // 51200 B
    if (!smem_set) {
        cudaFuncSetAttribute(attn_kernel,
                             cudaFuncAttributeMaxDynamicSharedMemorySize,
                             attn_smem);
        smem_set = 1;
    }
    attn_kernel<<<dim3(T_ / ABM, NH_, B_), 128, attn_smem>>>();

    // output projection
    gemm_kernel<<<dim3(M / GBM, 512 / GBN), 256>>>(ybuf, Wp, out, 512, 0);
}

// round 2
// speedup vs baseline: 1.0233x; 1.0233x over previous
#include <cuda_runtime.h>
#include <math.h>
#include <stdint.h>

// Problem constants
#define B_   8
#define T_   2048
#define DIM_ 512
#define NH_  8
#define NKV_ 4
#define HD_  64
#define EPS_ 1.1920928955078125e-07f
// log2(10000)/32
#define FREQ_C 0.41524101186091903f

typedef unsigned long long u64;

// ---------------- packed f32x2 helpers (SASS FFMA2 path) -------------------
__device__ __forceinline__ u64 ffma2(u64 a, u64 b, u64 c) {
    u64 d;
    asm("fma.rn.f32x2 %0, %1, %2, %3;" : "=l"(d) : "l"(a), "l"(b), "l"(c));
    return d;
}
__device__ __forceinline__ u64 fmul2(u64 a, u64 b) {
    u64 d;
    asm("mul.rn.f32x2 %0, %1, %2;" : "=l"(d) : "l"(a), "l"(b));
    return d;
}
__device__ __forceinline__ u64 pack2(float lo, float hi) {
    u64 d;
    asm("mov.b64 %0, {%1, %2};" : "=l"(d) : "f"(lo), "f"(hi));
    return d;
}
__device__ __forceinline__ float2 unpack2(u64 v) {
    float2 r;
    asm("mov.b64 {%0, %1}, %2;" : "=f"(r.x), "=f"(r.y) : "l"(v));
    return r;
}

// ---------------- scratch (device globals; no allocation allowed) ----------
__device__ float g_qkv[(size_t)B_ * T_ * 1024];        // raw q|k|v projections
__device__ float g_q[(size_t)B_ * NH_ * T_ * HD_];     // [b][h][t][d]
__device__ float g_k[(size_t)B_ * NKV_ * T_ * HD_];
__device__ float g_v[(size_t)B_ * NKV_ * T_ * HD_];
__device__ float g_y[(size_t)B_ * T_ * DIM_];          // attention output

// ---------------- GEMM: C[M][N] = A[M][512] @ W[N][512]^T ------------------
// grid (M/128, N/128), 256 threads, 8x8 register tile, f32x2 inner product
#define GBM 128
#define GBN 128
#define GBK 32

__global__ __launch_bounds__(256) void gemm_kernel(
    const float* __restrict__ A, const float* __restrict__ W,
    float* __restrict__ C, int ldc, int coff)
{
    __shared__ float Xs[GBK][GBM + 4];
    __shared__ float Ws[GBK][GBN + 4];

    const int m0 = blockIdx.x * GBM;
    const int n0 = blockIdx.y * GBN;
    const int tid = threadIdx.x;
    const int tm = (tid >> 4) << 3;   // 0..120
    const int tn = (tid & 15) << 3;   // 0..120

    u64 acc2[8][4];                   // [i][j-pair], 64 fp32 accumulators
#pragma unroll
    for (int i = 0; i < 8; i++)
#pragma unroll
        for (int j = 0; j < 4; j++) acc2[i][j] = 0ull;

    const int lr = tid >> 3;     // 0..31
    const int lc4 = tid & 7;     // 0..7  (float4 column)

    for (int k0 = 0; k0 < 512; k0 += GBK) {
#pragma unroll
        for (int p = 0; p < 4; p++) {
            int r = lr + p * 32;
            float4 av = *(const float4*)&A[(size_t)(m0 + r) * 512 + k0 + lc4 * 4];
            Xs[lc4 * 4 + 0][r] = av.x;
            Xs[lc4 * 4 + 1][r] = av.y;
            Xs[lc4 * 4 + 2][r] = av.z;
            Xs[lc4 * 4 + 3][r] = av.w;
            float4 wv = *(const float4*)&W[(size_t)(n0 + r) * 512 + k0 + lc4 * 4];
            Ws[lc4 * 4 + 0][r] = wv.x;
            Ws[lc4 * 4 + 1][r] = wv.y;
            Ws[lc4 * 4 + 2][r] = wv.z;
            Ws[lc4 * 4 + 3][r] = wv.w;
        }
        __syncthreads();

#pragma unroll
        for (int k = 0; k < GBK; k++) {
            // W pairs come straight out of smem as aligned 64-bit lanes
            ulonglong2 wa = *(const ulonglong2*)&Ws[k][tn];
            ulonglong2 wb = *(const ulonglong2*)&Ws[k][tn + 4];
            u64 wp[4] = {wa.x, wa.y, wb.x, wb.y};
            float4 xa = *(const float4*)&Xs[k][tm];
            float4 xb = *(const float4*)&Xs[k][tm + 4];
            float xv[8] = {xa.x, xa.y, xa.z, xa.w, xb.x, xb.y, xb.z, xb.w};
#pragma unroll
            for (int i = 0; i < 8; i++) {
                u64 xd = pack2(xv[i], xv[i]);
#pragma unroll
                for (int j = 0; j < 4; j++)
                    acc2[i][j] = ffma2(xd, wp[j], acc2[i][j]);
            }
        }
        __syncthreads();
    }

#pragma unroll
    for (int i = 0; i < 8; i++) {
        float* cp = C + (size_t)(m0 + tm + i) * ldc + coff + n0 + tn;
        float2 a0 = unpack2(acc2[i][0]);
        float2 a1 = unpack2(acc2[i][1]);
        float2 a2 = unpack2(acc2[i][2]);
        float2 a3 = unpack2(acc2[i][3]);
        *(float4*)cp       = make_float4(a0.x, a0.y, a1.x, a1.y);
        *(float4*)(cp + 4) = make_float4(a2.x, a2.y, a3.x, a3.y);
    }
}

// ---------------- RMSNorm + RoPE epilogue ---------------------------------
// one block per token; warp w handles q head w, warps 0..3 also k head w.
__device__ __forceinline__ void norm_rope_head(
    const float* __restrict__ src, float* __restrict__ dst,
    int lane, float cv, float sv)
{
    float x1 = src[lane];
    float x2 = src[lane + 32];
    float ss = x1 * x1 + x2 * x2;
#pragma unroll
    for (int off = 16; off > 0; off >>= 1)
        ss += __shfl_xor_sync(0xffffffffu, ss, off);
    float ir = rsqrtf(ss * (1.f / 64.f) + EPS_);
    x1 *= ir;
    x2 *= ir;
    dst[lane]      = x1 * cv + x2 * sv;
    dst[lane + 32] = x2 * cv - x1 * sv;
}

__global__ __launch_bounds__(256) void rope_kernel()
{
    const int tok = blockIdx.x;
    const int b = tok >> 11;
    const int t = tok & (T_ - 1);
    const int lane = threadIdx.x & 31;
    const int w = threadIdx.x >> 5;

    const float* row = g_qkv + (size_t)tok * 1024;

    float inv_freq = exp2f(-(float)lane * FREQ_C);
    float f = (float)t * inv_freq;
    float sv, cv;
    sincosf(f, &sv, &cv);   // precise version: args up to ~2048

    // q head w
    norm_rope_head(row + w * 64,
                   g_q + (((size_t)b * NH_ + w) * T_ + t) * HD_,
                   lane, cv, sv);
    // k head w (warps 0..3)
    if (w < 4) {
        norm_rope_head(row + 512 + w * 64,
                       g_k + (((size_t)b * NKV_ + w) * T_ + t) * HD_,
                       lane, cv, sv);
    }
    // v copy (each thread one element)
    {
        int i = threadIdx.x;           // 0..255
        int vh = i >> 6, d = i & 63;
        g_v[(((size_t)b * NKV_ + vh) * T_ + t) * HD_ + d] = row[768 + i];
    }
}

// ---------------- causal flash attention ----------------------------------
// grid (T/BM, NH, B), 128 threads, thread-per-query-row, BN=32 kv tiles.
// all inner products run on fma.rn.f32x2 with pairs loaded directly from smem.
#define ABM 128
#define ABN 32
#define QPAD 68   // Q row stride in smem (float4-aligned, conflict-free)

__global__ __launch_bounds__(128) void attn_kernel()
{
    extern __shared__ float sm[];
    float* Qs = sm;                       // ABM x QPAD
    float* Ks = sm + ABM * QPAD;          // ABN x 64 (broadcast reads; no pad)
    float* Vs = Ks + ABN * HD_;           // ABN x 64

    const int tid = threadIdx.x;
    // heavy q-tiles first (better tail behavior under causal imbalance)
    const int q0 = (gridDim.x - 1 - blockIdx.x) * ABM;
    const int h = blockIdx.y;
    const int b = blockIdx.z;
    const int kvh = h >> 1;               // GQA: rep = 2

    // load Q tile (coalesced float4)
    {
        const float* qb = g_q + (((size_t)b * NH_ + h) * T_ + q0) * HD_;
#pragma unroll
        for (int p = 0; p < 16; p++) {
            int i = tid + p * 128;        // 0..2047 float4 index
            int row = i >> 4, c4 = i & 15;
            *(float4*)(Qs + row * QPAD + c4 * 4) =
                ((const float4*)qb)[i];
        }
    }
    __syncthreads();

    const int r = tid;                    // query row within tile
    const int gi = q0 + r;                // global query index
    float m = -INFINITY, l = 0.f;
    u64 O2[HD_ / 2];                      // output pairs along d
#pragma unroll
    for (int d = 0; d < HD_ / 2; d++) O2[d] = 0ull;

    const float* kb0 = g_k + (((size_t)b * NKV_ + kvh) * T_) * HD_;
    const float* vb0 = g_v + (((size_t)b * NKV_ + kvh) * T_) * HD_;

    const int nkt = q0 / ABN + ABM / ABN; // tiles covering j <= q0+127

    for (int kt = 0; kt < nkt; kt++) {
        // load K/V tile (coalesced; 512 float4 each over 128 threads)
        {
            const float4* kp = (const float4*)(kb0 + (size_t)kt * ABN * HD_);
            const float4* vp = (const float4*)(vb0 + (size_t)kt * ABN * HD_);
#pragma unroll
            for (int p = 0; p < 4; p++) {
                int i = tid + p * 128;    // 0..511
                ((float4*)Ks)[i] = kp[i];
                ((float4*)Vs)[i] = vp[i];
            }
        }
        __syncthreads();

        // scores S = Q . K^T   (2-wide partial sums, FFMA2)
        u64 S2[ABN];
#pragma unroll
        for (int c = 0; c < ABN; c++) S2[c] = 0ull;
#pragma unroll 4
        for (int d4 = 0; d4 < 16; d4++) {
            ulonglong2 q2 = *(const ulonglong2*)(Qs + r * QPAD + d4 * 4);
#pragma unroll
            for (int c = 0; c < ABN; c++) {
                ulonglong2 k2 = *(const ulonglong2*)(Ks + c * HD_ + d4 * 4);
                S2[c] = ffma2(q2.x, k2.x, S2[c]);
                S2[c] = ffma2(q2.y, k2.y, S2[c]);
            }
        }

        // horizontal add + scale + causal mask + online softmax
        const int jb = kt * ABN;
        float S[ABN];
        float tmax = -INFINITY;
#pragma unroll
        for (int c = 0; c < ABN; c++) {
            float2 p2 = unpack2(S2[c]);
            float sc = (p2.x + p2.y) * 0.125f;
            if (jb + c > gi) sc = -INFINITY;
            S[c] = sc;
            tmax = fmaxf(tmax, sc);
        }
        float mnew = fmaxf(m, tmax);
        float corr = __expf(m - mnew);
        float psum = 0.f;
#pragma unroll
        for (int c = 0; c < ABN; c++) {
            float p = __expf(S[c] - mnew);
            S[c] = p;
            psum += p;
        }
        l = l * corr + psum;
        m = mnew;
        u64 corr2 = pack2(corr, corr);
#pragma unroll
        for (int d = 0; d < HD_ / 2; d++) O2[d] = fmul2(O2[d], corr2);

        // O += P @ V  (FFMA2, V pairs straight from smem)
#pragma unroll
        for (int c = 0; c < ABN; c++) {
            u64 pd = pack2(S[c], S[c]);
#pragma unroll
            for (int d4 = 0; d4 < 16; d4++) {
                ulonglong2 v2 = *(const ulonglong2*)(Vs + c * HD_ + d4 * 4);
                O2[d4 * 2 + 0] = ffma2(pd, v2.x, O2[d4 * 2 + 0]);
                O2[d4 * 2 + 1] = ffma2(pd, v2.y, O2[d4 * 2 + 1]);
            }
        }
        __syncthreads();
    }

    // normalize and stage into smem for coalesced writeback
    float inv_l = 1.f / l;
    u64 il2 = pack2(inv_l, inv_l);
#pragma unroll
    for (int d2 = 0; d2 < HD_ / 2; d2++) {
        float2 o = unpack2(fmul2(O2[d2], il2));
        *(float2*)(Qs + r * QPAD + d2 * 2) = o;
    }
    __syncthreads();

    float* yb = g_y + ((size_t)b * T_ + q0) * DIM_ + h * HD_;
#pragma unroll
    for (int p = 0; p < 16; p++) {
        int i = tid + p * 128;
        int row = i >> 4, c4 = i & 15;
        *(float4*)(yb + (size_t)row * DIM_ + c4 * 4) =
            *(const float4*)(Qs + row * QPAD + c4 * 4);
    }
}

// ---------------- launch ---------------------------------------------------
extern "C" void kernel_launch(void* const* d_in, const int* in_sizes, int n_in,
                              void* d_out, int out_size)
{
    const float* x  = (const float*)d_in[0];
    const float* Wq = (const float*)d_in[1];
    const float* Wk = (const float*)d_in[2];
    const float* Wv = (const float*)d_in[3];
    const float* Wp = (const float*)d_in[4];
    float* out = (float*)d_out;

    float* qkv;  cudaGetSymbolAddress((void**)&qkv, g_qkv);
    float* ybuf; cudaGetSymbolAddress((void**)&ybuf, g_y);

    const int M = B_ * T_;  // 16384

    // QKV projections into g_qkv (q|k|v columns)
    gemm_kernel<<<dim3(M / GBM, 512 / GBN), 256>>>(x, Wq, qkv, 1024, 0);
    gemm_kernel<<<dim3(M / GBM, 256 / GBN), 256>>>(x, Wk, qkv, 1024, 512);
    gemm_kernel<<<dim3(M / GBM, 256 / GBN), 256>>>(x, Wv, qkv, 1024, 768);

    // RMSNorm + RoPE + scatter to [b][h][t][d]
    rope_kernel<<<M, 256>>>();

    // attention
    static int smem_set = 0;
    const int attn_smem = (ABM * QPAD + 2 * ABN * HD_) * sizeof(float); // 51200 B
    if (!smem_set) {
        cudaFuncSetAttribute(attn_kernel,
                             cudaFuncAttributeMaxDynamicSharedMemorySize,
                             attn_smem);
        smem_set = 1;
    }
    attn_kernel<<<dim3(T_ / ABM, NH_, B_), 128, attn_smem>>>();

    // output projection
    gemm_kernel<<<dim3(M / GBM, 512 / GBN), 256>>>(ybuf, Wp, out, 512, 0);
}

// round 3
// speedup vs baseline: 1.1990x; 1.1717x over previous
#include <cuda_runtime.h>
#include <cuda_bf16.h>
#include <math.h>
#include <stdint.h>

// Problem constants
#define B_   8
#define T_   2048
#define DIM_ 512
#define NH_  8
#define NKV_ 4
#define HD_  64
#define EPS_ 1.1920928955078125e-07f
#define FREQ_C 0.41524101186091903f   // log2(10000)/32

typedef unsigned long long u64;
typedef uint32_t u32;

// ---------------- packed f32x2 helpers (kept for attention) ---------------
__device__ __forceinline__ u64 ffma2(u64 a, u64 b, u64 c) {
    u64 d;
    asm("fma.rn.f32x2 %0, %1, %2, %3;" : "=l"(d) : "l"(a), "l"(b), "l"(c));
    return d;
}
__device__ __forceinline__ u64 fmul2(u64 a, u64 b) {
    u64 d;
    asm("mul.rn.f32x2 %0, %1, %2;" : "=l"(d) : "l"(a), "l"(b));
    return d;
}
__device__ __forceinline__ u64 pack2(float lo, float hi) {
    u64 d;
    asm("mov.b64 %0, {%1, %2};" : "=l"(d) : "f"(lo), "f"(hi));
    return d;
}
__device__ __forceinline__ float2 unpack2(u64 v) {
    float2 r;
    asm("mov.b64 {%0, %1}, %2;" : "=f"(r.x), "=f"(r.y) : "l"(v));
    return r;
}

// ---------------- scratch (device globals; no allocation allowed) ----------
__device__ float g_qkv[(size_t)B_ * T_ * 1024];        // raw q|k|v projections
__device__ float g_q[(size_t)B_ * NH_ * T_ * HD_];     // [b][h][t][d]
__device__ float g_k[(size_t)B_ * NKV_ * T_ * HD_];
__device__ float g_v[(size_t)B_ * NKV_ * T_ * HD_];
__device__ float g_y[(size_t)B_ * T_ * DIM_];          // attention output

// bf16 split operands
__device__ __nv_bfloat16 g_xh[(size_t)B_ * T_ * DIM_];
__device__ __nv_bfloat16 g_xl[(size_t)B_ * T_ * DIM_];
__device__ __nv_bfloat16 g_yh[(size_t)B_ * T_ * DIM_];
__device__ __nv_bfloat16 g_yl[(size_t)B_ * T_ * DIM_];
// combined weights: rows [0,512)=Wq, [512,768)=Wk, [768,1024)=Wv, [1024,1536)=Wp
__device__ __nv_bfloat16 g_wh[(size_t)1536 * DIM_];
__device__ __nv_bfloat16 g_wl[(size_t)1536 * DIM_];

// ---------------- split fp32 -> bf16 hi/lo --------------------------------
__global__ __launch_bounds__(256) void split_kernel(
    const float* __restrict__ src, __nv_bfloat16* __restrict__ h,
    __nv_bfloat16* __restrict__ l)
{
    int i = blockIdx.x * 256 + threadIdx.x;
    float x = src[i];
    __nv_bfloat16 hh = __float2bfloat16(x);
    float r = x - __bfloat162float(hh);
    h[i] = hh;
    l[i] = __float2bfloat16(r);
}

// ---------------- bf16-split tensor-core GEMM -----------------------------
// C[M][N](+coff) = A[M][512] @ W[N][512]^T, 3-term compensated bf16.
// block: 128M x 128N, 256 threads (8 warps, 2x4), warp tile 64x32.
#define LDSB 40   // smem row stride in bf16 (conflict-free for frag loads)

__device__ __forceinline__ u32 lds32(const __nv_bfloat16* s, int row, int k) {
    return *(const u32*)(s + row * LDSB + k);
}

__device__ __forceinline__ void mma_bf16(float* c, const u32* a, u32 b0, u32 b1) {
    asm volatile(
        "mma.sync.aligned.m16n8k16.row.col.f32.bf16.bf16.f32 "
        "{%0,%1,%2,%3}, {%4,%5,%6,%7}, {%8,%9}, {%0,%1,%2,%3};\n"
        : "+f"(c[0]), "+f"(c[1]), "+f"(c[2]), "+f"(c[3])
        : "r"(a[0]), "r"(a[1]), "r"(a[2]), "r"(a[3]), "r"(b0), "r"(b1));
}

__global__ __launch_bounds__(256) void gemm_bf16_kernel(
    const __nv_bfloat16* __restrict__ Ah, const __nv_bfloat16* __restrict__ Al,
    int wrow0, float* __restrict__ C, int ldc, int coff)
{
    __shared__ __nv_bfloat16 sAh[128 * LDSB];
    __shared__ __nv_bfloat16 sAl[128 * LDSB];
    __shared__ __nv_bfloat16 sWh[128 * LDSB];
    __shared__ __nv_bfloat16 sWl[128 * LDSB];

    const int tid  = threadIdx.x;
    const int m0   = blockIdx.x * 128;
    const int n0   = blockIdx.y * 128;
    const int lane = tid & 31;
    const int wid  = tid >> 5;
    const int wm   = (wid >> 2) * 64;     // warp M offset
    const int wn   = (wid & 3) * 32;      // warp N offset
    const int g    = lane >> 2;           // group 0..7
    const int t2   = (lane & 3) * 2;      // 0,2,4,6

    const __nv_bfloat16* Wh = g_wh + (size_t)wrow0 * 512;
    const __nv_bfloat16* Wl = g_wl + (size_t)wrow0 * 512;

    float acc[4][4][4];
#pragma unroll
    for (int i = 0; i < 4; i++)
#pragma unroll
        for (int j = 0; j < 4; j++)
#pragma unroll
            for (int q = 0; q < 4; q++) acc[i][j][q] = 0.f;

    // loader mapping: 512 uint4 per tile, 2 per thread per tile
    const int l_row0 = tid >> 2;          // 0..63
    const int l_c4   = tid & 3;           // 0..3 (uint4 col: 8 bf16 each)

    uint4 pAh[2], pAl[2], pWh[2], pWl[2];

    // prefetch k0 = 0
#pragma unroll
    for (int p = 0; p < 2; p++) {
        int row = l_row0 + p * 64;
        size_t ao = (size_t)(m0 + row) * 512 + l_c4 * 8;
        size_t wo = (size_t)(n0 + row) * 512 + l_c4 * 8;
        pAh[p] = *(const uint4*)(Ah + ao);
        pAl[p] = *(const uint4*)(Al + ao);
        pWh[p] = *(const uint4*)(Wh + wo);
        pWl[p] = *(const uint4*)(Wl + wo);
    }

    for (int it = 0; it < 16; it++) {
#pragma unroll
        for (int p = 0; p < 2; p++) {
            int row = l_row0 + p * 64;
            int so = row * LDSB + l_c4 * 8;
            *(uint4*)(sAh + so) = pAh[p];
            *(uint4*)(sAl + so) = pAl[p];
            *(uint4*)(sWh + so) = pWh[p];
            *(uint4*)(sWl + so) = pWl[p];
        }
        __syncthreads();

        if (it < 15) {
            int k0 = (it + 1) * 32;
#pragma unroll
            for (int p = 0; p < 2; p++) {
                int row = l_row0 + p * 64;
                size_t ao = (size_t)(m0 + row) * 512 + k0 + l_c4 * 8;
                size_t wo = (size_t)(n0 + row) * 512 + k0 + l_c4 * 8;
                pAh[p] = *(const uint4*)(Ah + ao);
                pAl[p] = *(const uint4*)(Al + ao);
                pWh[p] = *(const uint4*)(Wh + wo);
                pWl[p] = *(const uint4*)(Wl + wo);
            }
        }

#pragma unroll
        for (int ks = 0; ks < 32; ks += 16) {
            u32 ah[4][4], al[4][4];
#pragma unroll
            for (int mt = 0; mt < 4; mt++) {
                int r = wm + mt * 16;
                ah[mt][0] = lds32(sAh, r + g,     ks + t2);
                ah[mt][1] = lds32(sAh, r + g + 8, ks + t2);
                ah[mt][2] = lds32(sAh, r + g,     ks + t2 + 8);
                ah[mt][3] = lds32(sAh, r + g + 8, ks + t2 + 8);
                al[mt][0] = lds32(sAl, r + g,     ks + t2);
                al[mt][1] = lds32(sAl, r + g + 8, ks + t2);
                al[mt][2] = lds32(sAl, r + g,     ks + t2 + 8);
                al[mt][3] = lds32(sAl, r + g + 8, ks + t2 + 8);
            }
#pragma unroll
            for (int nt = 0; nt < 4; nt++) {
                int c = wn + nt * 8 + g;
                u32 bh0 = lds32(sWh, c, ks + t2);
                u32 bh1 = lds32(sWh, c, ks + t2 + 8);
                u32 bl0 = lds32(sWl, c, ks + t2);
                u32 bl1 = lds32(sWl, c, ks + t2 + 8);
#pragma unroll
                for (int mt = 0; mt < 4; mt++) {
                    mma_bf16(acc[mt][nt], ah[mt], bh0, bh1);
                    mma_bf16(acc[mt][nt], ah[mt], bl0, bl1);
                    mma_bf16(acc[mt][nt], al[mt], bh0, bh1);
                }
            }
        }
        __syncthreads();
    }

    // epilogue: c0:(g,2t) c1:(g,2t+1) c2:(g+8,2t) c3:(g+8,2t+1)
#pragma unroll
    for (int mt = 0; mt < 4; mt++) {
#pragma unroll
        for (int nt = 0; nt < 4; nt++) {
            int row = m0 + wm + mt * 16 + g;
            int col = coff + n0 + wn + nt * 8 + t2;
            float* c = acc[mt][nt];
            *(float2*)&C[(size_t)row * ldc + col] = make_float2(c[0], c[1]);
            *(float2*)&C[(size_t)(row + 8) * ldc + col] = make_float2(c[2], c[3]);
        }
    }
}

// ---------------- RMSNorm + RoPE epilogue ---------------------------------
__device__ __forceinline__ void norm_rope_head(
    const float* __restrict__ src, float* __restrict__ dst,
    int lane, float cv, float sv)
{
    float x1 = src[lane];
    float x2 = src[lane + 32];
    float ss = x1 * x1 + x2 * x2;
#pragma unroll
    for (int off = 16; off > 0; off >>= 1)
        ss += __shfl_xor_sync(0xffffffffu, ss, off);
    float ir = rsqrtf(ss * (1.f / 64.f) + EPS_);
    x1 *= ir;
    x2 *= ir;
    dst[lane]      = x1 * cv + x2 * sv;
    dst[lane + 32] = x2 * cv - x1 * sv;
}

__global__ __launch_bounds__(256) void rope_kernel()
{
    const int tok = blockIdx.x;
    const int b = tok >> 11;
    const int t = tok & (T_ - 1);
    const int lane = threadIdx.x & 31;
    const int w = threadIdx.x >> 5;

    const float* row = g_qkv + (size_t)tok * 1024;

    float inv_freq = exp2f(-(float)lane * FREQ_C);
    float f = (float)t * inv_freq;
    float sv, cv;
    sincosf(f, &sv, &cv);

    norm_rope_head(row + w * 64,
                   g_q + (((size_t)b * NH_ + w) * T_ + t) * HD_,
                   lane, cv, sv);
    if (w < 4) {
        norm_rope_head(row + 512 + w * 64,
                       g_k + (((size_t)b * NKV_ + w) * T_ + t) * HD_,
                       lane, cv, sv);
    }
    {
        int i = threadIdx.x;
        int vh = i >> 6, d = i & 63;
        g_v[(((size_t)b * NKV_ + vh) * T_ + t) * HD_ + d] = row[768 + i];
    }
}

// ---------------- causal flash attention (fp32, unchanged from R1) --------
#define ABM 128
#define ABN 32
#define QPAD 68

__global__ __launch_bounds__(128) void attn_kernel()
{
    extern __shared__ float sm[];
    float* Qs = sm;
    float* Ks = sm + ABM * QPAD;
    float* Vs = Ks + ABN * HD_;

    const int tid = threadIdx.x;
    const int q0 = (gridDim.x - 1 - blockIdx.x) * ABM;
    const int h = blockIdx.y;
    const int b = blockIdx.z;
    const int kvh = h >> 1;

    {
        const float* qb = g_q + (((size_t)b * NH_ + h) * T_ + q0) * HD_;
#pragma unroll
        for (int p = 0; p < 16; p++) {
            int i = tid + p * 128;
            int row = i >> 4, c4 = i & 15;
            *(float4*)(Qs + row * QPAD + c4 * 4) = ((const float4*)qb)[i];
        }
    }
    __syncthreads();

    const int r = tid;
    const int gi = q0 + r;
    float m = -INFINITY, l = 0.f;
    u64 O2[HD_ / 2];
#pragma unroll
    for (int d = 0; d < HD_ / 2; d++) O2[d] = 0ull;

    const float* kb0 = g_k + (((size_t)b * NKV_ + kvh) * T_) * HD_;
    const float* vb0 = g_v + (((size_t)b * NKV_ + kvh) * T_) * HD_;

    const int nkt = q0 / ABN + ABM / ABN;

    for (int kt = 0; kt < nkt; kt++) {
        {
            const float4* kp = (const float4*)(kb0 + (size_t)kt * ABN * HD_);
            const float4* vp = (const float4*)(vb0 + (size_t)kt * ABN * HD_);
#pragma unroll
            for (int p = 0; p < 4; p++) {
                int i = tid + p * 128;
                ((float4*)Ks)[i] = kp[i];
                ((float4*)Vs)[i] = vp[i];
            }
        }
        __syncthreads();

        u64 S2[ABN];
#pragma unroll
        for (int c = 0; c < ABN; c++) S2[c] = 0ull;
#pragma unroll 4
        for (int d4 = 0; d4 < 16; d4++) {
            ulonglong2 q2 = *(const ulonglong2*)(Qs + r * QPAD + d4 * 4);
#pragma unroll
            for (int c = 0; c < ABN; c++) {
                ulonglong2 k2 = *(const ulonglong2*)(Ks + c * HD_ + d4 * 4);
                S2[c] = ffma2(q2.x, k2.x, S2[c]);
                S2[c] = ffma2(q2.y, k2.y, S2[c]);
            }
        }

        const int jb = kt * ABN;
        float S[ABN];
        float tmax = -INFINITY;
#pragma unroll
        for (int c = 0; c < ABN; c++) {
            float2 p2 = unpack2(S2[c]);
            float sc = (p2.x + p2.y) * 0.125f;
            if (jb + c > gi) sc = -INFINITY;
            S[c] = sc;
            tmax = fmaxf(tmax, sc);
        }
        float mnew = fmaxf(m, tmax);
        float corr = __expf(m - mnew);
        float psum = 0.f;
#pragma unroll
        for (int c = 0; c < ABN; c++) {
            float p = __expf(S[c] - mnew);
            S[c] = p;
            psum += p;
        }
        l = l * corr + psum;
        m = mnew;
        u64 corr2 = pack2(corr, corr);
#pragma unroll
        for (int d = 0; d < HD_ / 2; d++) O2[d] = fmul2(O2[d], corr2);

#pragma unroll
        for (int c = 0; c < ABN; c++) {
            u64 pd = pack2(S[c], S[c]);
#pragma unroll
            for (int d4 = 0; d4 < 16; d4++) {
                ulonglong2 v2 = *(const ulonglong2*)(Vs + c * HD_ + d4 * 4);
                O2[d4 * 2 + 0] = ffma2(pd, v2.x, O2[d4 * 2 + 0]);
                O2[d4 * 2 + 1] = ffma2(pd, v2.y, O2[d4 * 2 + 1]);
            }
        }
        __syncthreads();
    }

    float inv_l = 1.f / l;
    u64 il2 = pack2(inv_l, inv_l);
#pragma unroll
    for (int d2 = 0; d2 < HD_ / 2; d2++) {
        float2 o = unpack2(fmul2(O2[d2], il2));
        *(float2*)(Qs + r * QPAD + d2 * 2) = o;
    }
    __syncthreads();

    float* yb = g_y + ((size_t)b * T_ + q0) * DIM_ + h * HD_;
#pragma unroll
    for (int p = 0; p < 16; p++) {
        int i = tid + p * 128;
        int row = i >> 4, c4 = i & 15;
        *(float4*)(yb + (size_t)row * DIM_ + c4 * 4) =
            *(const float4*)(Qs + row * QPAD + c4 * 4);
    }
}

// ---------------- launch ---------------------------------------------------
extern "C" void kernel_launch(void* const* d_in, const int* in_sizes, int n_in,
                              void* d_out, int out_size)
{
    const float* x  = (const float*)d_in[0];
    const float* Wq = (const float*)d_in[1];
    const float* Wk = (const float*)d_in[2];
    const float* Wv = (const float*)d_in[3];
    const float* Wp = (const float*)d_in[4];
    float* out = (float*)d_out;

    float* qkv;  cudaGetSymbolAddress((void**)&qkv, g_qkv);
    float* ybuf; cudaGetSymbolAddress((void**)&ybuf, g_y);
    __nv_bfloat16 *xh, *xl, *yh, *yl, *wh, *wl;
    cudaGetSymbolAddress((void**)&xh, g_xh);
    cudaGetSymbolAddress((void**)&xl, g_xl);
    cudaGetSymbolAddress((void**)&yh, g_yh);
    cudaGetSymbolAddress((void**)&yl, g_yl);
    cudaGetSymbolAddress((void**)&wh, g_wh);
    cudaGetSymbolAddress((void**)&wl, g_wl);

    const int M = B_ * T_;  // 16384

    // split inputs/weights into bf16 hi/lo
    split_kernel<<<(M * DIM_) / 256, 256>>>(x, xh, xl);
    split_kernel<<<(512 * 512) / 256, 256>>>(Wq, wh, wl);
    split_kernel<<<(256 * 512) / 256, 256>>>(Wk, wh + (size_t)512 * 512,
                                             wl + (size_t)512 * 512);
    split_kernel<<<(256 * 512) / 256, 256>>>(Wv, wh + (size_t)768 * 512,
                                             wl + (size_t)768 * 512);
    split_kernel<<<(512 * 512) / 256, 256>>>(Wp, wh + (size_t)1024 * 512,
                                             wl + (size_t)1024 * 512);

    // fused QKV projection (combined weight rows 0..1023)
    gemm_bf16_kernel<<<dim3(M / 128, 8), 256>>>(xh, xl, 0, qkv, 1024, 0);

    // RMSNorm + RoPE + scatter
    rope_kernel<<<M, 256>>>();

    // attention
    static int smem_set = 0;
    const int attn_smem = (ABM * QPAD + 2 * ABN * HD_) * sizeof(float);
    if (!smem_set) {
        cudaFuncSetAttribute(attn_kernel,
                             cudaFuncAttributeMaxDynamicSharedMemorySize,
                             attn_smem);
        smem_set = 1;
    }
    attn_kernel<<<dim3(T_ / ABM, NH_, B_), 128, attn_smem>>>();

    // output projection (weight rows 1024..1535)
    split_kernel<<<(M * DIM_) / 256, 256>>>(ybuf, yh, yl);
    gemm_bf16_kernel<<<dim3(M / 128, 4), 256>>>(yh, yl, 1024, out, 512, 0);
}

// round 4
// speedup vs baseline: 2.4892x; 2.0760x over previous
#include <cuda_runtime.h>
#include <cuda_bf16.h>
#include <math.h>
#include <stdint.h>

// Problem constants
#define B_   8
#define T_   2048
#define DIM_ 512
#define NH_  8
#define NKV_ 4
#define HD_  64
#define EPS_ 1.1920928955078125e-07f
#define FREQ_C 0.41524101186091903f   // log2(10000)/32

typedef unsigned long long u64;
typedef uint32_t u32;

// ---------------- scratch (device globals; no allocation allowed) ----------
__device__ float g_qkv[(size_t)B_ * T_ * 1024];        // raw q|k|v projections
__device__ float g_y[(size_t)B_ * T_ * DIM_];          // attention output

// bf16 split operands for projections
__device__ __nv_bfloat16 g_xh[(size_t)B_ * T_ * DIM_];
__device__ __nv_bfloat16 g_xl[(size_t)B_ * T_ * DIM_];
__device__ __nv_bfloat16 g_yh[(size_t)B_ * T_ * DIM_];
__device__ __nv_bfloat16 g_yl[(size_t)B_ * T_ * DIM_];
__device__ __nv_bfloat16 g_wh[(size_t)1536 * DIM_];
__device__ __nv_bfloat16 g_wl[(size_t)1536 * DIM_];

// bf16 split attention operands
__device__ __nv_bfloat16 g_qh[(size_t)B_ * NH_ * T_ * HD_];   // [b][h][t][d], scaled 1/8
__device__ __nv_bfloat16 g_ql[(size_t)B_ * NH_ * T_ * HD_];
__device__ __nv_bfloat16 g_kh[(size_t)B_ * NKV_ * T_ * HD_];  // [b][kv][t][d]
__device__ __nv_bfloat16 g_kl[(size_t)B_ * NKV_ * T_ * HD_];
__device__ __nv_bfloat16 g_vth[(size_t)B_ * NKV_ * HD_ * T_]; // [b][kv][d][t]
__device__ __nv_bfloat16 g_vtl[(size_t)B_ * NKV_ * HD_ * T_];

// ---------------- small helpers -------------------------------------------
__device__ __forceinline__ u32 cvt2bf(float lo, float hi) {
    u32 r;
    asm("cvt.rn.bf16x2.f32 %0, %1, %2;" : "=r"(r) : "f"(hi), "f"(lo));
    return r;
}

__device__ __forceinline__ void mma_bf16(float* c, const u32* a, u32 b0, u32 b1) {
    asm volatile(
        "mma.sync.aligned.m16n8k16.row.col.f32.bf16.bf16.f32 "
        "{%0,%1,%2,%3}, {%4,%5,%6,%7}, {%8,%9}, {%0,%1,%2,%3};\n"
        : "+f"(c[0]), "+f"(c[1]), "+f"(c[2]), "+f"(c[3])
        : "r"(a[0]), "r"(a[1]), "r"(a[2]), "r"(a[3]), "r"(b0), "r"(b1));
}

// ---------------- split fp32 -> bf16 hi/lo --------------------------------
__global__ __launch_bounds__(256) void split_kernel(
    const float* __restrict__ src, __nv_bfloat16* __restrict__ h,
    __nv_bfloat16* __restrict__ l)
{
    int i = blockIdx.x * 256 + threadIdx.x;
    float x = src[i];
    __nv_bfloat16 hh = __float2bfloat16(x);
    float r = x - __bfloat162float(hh);
    h[i] = hh;
    l[i] = __float2bfloat16(r);
}

// ---------------- bf16-split tensor-core GEMM (unchanged from R2) ---------
#define LDSB 40

__device__ __forceinline__ u32 lds32(const __nv_bfloat16* s, int row, int k) {
    return *(const u32*)(s + row * LDSB + k);
}

__global__ __launch_bounds__(256) void gemm_bf16_kernel(
    const __nv_bfloat16* __restrict__ Ah, const __nv_bfloat16* __restrict__ Al,
    int wrow0, float* __restrict__ C, int ldc, int coff)
{
    __shared__ __nv_bfloat16 sAh[128 * LDSB];
    __shared__ __nv_bfloat16 sAl[128 * LDSB];
    __shared__ __nv_bfloat16 sWh[128 * LDSB];
    __shared__ __nv_bfloat16 sWl[128 * LDSB];

    const int tid  = threadIdx.x;
    const int m0   = blockIdx.x * 128;
    const int n0   = blockIdx.y * 128;
    const int lane = tid & 31;
    const int wid  = tid >> 5;
    const int wm   = (wid >> 2) * 64;
    const int wn   = (wid & 3) * 32;
    const int g    = lane >> 2;
    const int t2   = (lane & 3) * 2;

    const __nv_bfloat16* Wh = g_wh + (size_t)wrow0 * 512;
    const __nv_bfloat16* Wl = g_wl + (size_t)wrow0 * 512;

    float acc[4][4][4];
#pragma unroll
    for (int i = 0; i < 4; i++)
#pragma unroll
        for (int j = 0; j < 4; j++)
#pragma unroll
            for (int q = 0; q < 4; q++) acc[i][j][q] = 0.f;

    const int l_row0 = tid >> 2;
    const int l_c4   = tid & 3;

    uint4 pAh[2], pAl[2], pWh[2], pWl[2];
#pragma unroll
    for (int p = 0; p < 2; p++) {
        int row = l_row0 + p * 64;
        size_t ao = (size_t)(m0 + row) * 512 + l_c4 * 8;
        size_t wo = (size_t)(n0 + row) * 512 + l_c4 * 8;
        pAh[p] = *(const uint4*)(Ah + ao);
        pAl[p] = *(const uint4*)(Al + ao);
        pWh[p] = *(const uint4*)(Wh + wo);
        pWl[p] = *(const uint4*)(Wl + wo);
    }

    for (int it = 0; it < 16; it++) {
#pragma unroll
        for (int p = 0; p < 2; p++) {
            int row = l_row0 + p * 64;
            int so = row * LDSB + l_c4 * 8;
            *(uint4*)(sAh + so) = pAh[p];
            *(uint4*)(sAl + so) = pAl[p];
            *(uint4*)(sWh + so) = pWh[p];
            *(uint4*)(sWl + so) = pWl[p];
        }
        __syncthreads();

        if (it < 15) {
            int k0 = (it + 1) * 32;
#pragma unroll
            for (int p = 0; p < 2; p++) {
                int row = l_row0 + p * 64;
                size_t ao = (size_t)(m0 + row) * 512 + k0 + l_c4 * 8;
                size_t wo = (size_t)(n0 + row) * 512 + k0 + l_c4 * 8;
                pAh[p] = *(const uint4*)(Ah + ao);
                pAl[p] = *(const uint4*)(Al + ao);
                pWh[p] = *(const uint4*)(Wh + wo);
                pWl[p] = *(const uint4*)(Wl + wo);
            }
        }

#pragma unroll
        for (int ks = 0; ks < 32; ks += 16) {
            u32 ah[4][4], al[4][4];
#pragma unroll
            for (int mt = 0; mt < 4; mt++) {
                int r = wm + mt * 16;
                ah[mt][0] = lds32(sAh, r + g,     ks + t2);
                ah[mt][1] = lds32(sAh, r + g + 8, ks + t2);
                ah[mt][2] = lds32(sAh, r + g,     ks + t2 + 8);
                ah[mt][3] = lds32(sAh, r + g + 8, ks + t2 + 8);
                al[mt][0] = lds32(sAl, r + g,     ks + t2);
                al[mt][1] = lds32(sAl, r + g + 8, ks + t2);
                al[mt][2] = lds32(sAl, r + g,     ks + t2 + 8);
                al[mt][3] = lds32(sAl, r + g + 8, ks + t2 + 8);
            }
#pragma unroll
            for (int nt = 0; nt < 4; nt++) {
                int c = wn + nt * 8 + g;
                u32 bh0 = lds32(sWh, c, ks + t2);
                u32 bh1 = lds32(sWh, c, ks + t2 + 8);
                u32 bl0 = lds32(sWl, c, ks + t2);
                u32 bl1 = lds32(sWl, c, ks + t2 + 8);
#pragma unroll
                for (int mt = 0; mt < 4; mt++) {
                    mma_bf16(acc[mt][nt], ah[mt], bh0, bh1);
                    mma_bf16(acc[mt][nt], ah[mt], bl0, bl1);
                    mma_bf16(acc[mt][nt], al[mt], bh0, bh1);
                }
            }
        }
        __syncthreads();
    }

#pragma unroll
    for (int mt = 0; mt < 4; mt++) {
#pragma unroll
        for (int nt = 0; nt < 4; nt++) {
            int row = m0 + wm + mt * 16 + g;
            int col = coff + n0 + wn + nt * 8 + t2;
            float* c = acc[mt][nt];
            *(float2*)&C[(size_t)row * ldc + col] = make_float2(c[0], c[1]);
            *(float2*)&C[(size_t)(row + 8) * ldc + col] = make_float2(c[2], c[3]);
        }
    }
}

// ---------------- RMSNorm + RoPE -> split bf16 Q/K ------------------------
__device__ __forceinline__ void norm_rope_split(
    const float* __restrict__ src, __nv_bfloat16* __restrict__ dh,
    __nv_bfloat16* __restrict__ dl, int lane, float cv, float sv, float scale)
{
    float x1 = src[lane];
    float x2 = src[lane + 32];
    float ss = x1 * x1 + x2 * x2;
#pragma unroll
    for (int off = 16; off > 0; off >>= 1)
        ss += __shfl_xor_sync(0xffffffffu, ss, off);
    float ir = rsqrtf(ss * (1.f / 64.f) + EPS_) * scale;
    x1 *= ir;
    x2 *= ir;
    float o1 = x1 * cv + x2 * sv;
    float o2 = x2 * cv - x1 * sv;
    __nv_bfloat16 h1 = __float2bfloat16(o1);
    __nv_bfloat16 h2 = __float2bfloat16(o2);
    dh[lane]      = h1;
    dh[lane + 32] = h2;
    dl[lane]      = __float2bfloat16(o1 - __bfloat162float(h1));
    dl[lane + 32] = __float2bfloat16(o2 - __bfloat162float(h2));
}

__global__ __launch_bounds__(256) void rope_kernel()
{
    const int tok = blockIdx.x;
    const int b = tok >> 11;
    const int t = tok & (T_ - 1);
    const int lane = threadIdx.x & 31;
    const int w = threadIdx.x >> 5;

    const float* row = g_qkv + (size_t)tok * 1024;

    float inv_freq = exp2f(-(float)lane * FREQ_C);
    float f = (float)t * inv_freq;
    float sv, cv;
    sincosf(f, &sv, &cv);

    size_t qo = (((size_t)b * NH_ + w) * T_ + t) * HD_;
    norm_rope_split(row + w * 64, g_qh + qo, g_ql + qo, lane, cv, sv, 0.125f);
    if (w < 4) {
        size_t ko = (((size_t)b * NKV_ + w) * T_ + t) * HD_;
        norm_rope_split(row + 512 + w * 64, g_kh + ko, g_kl + ko,
                        lane, cv, sv, 1.0f);
    }
}

// ---------------- V transpose + split: g_qkv -> [b][kv][d][t] bf16 --------
__global__ __launch_bounds__(256) void vtrans_kernel()
{
    __shared__ float vs[64][65];
    const int tid = threadIdx.x;
    const int t0 = blockIdx.x * 64;
    const int kv = blockIdx.y;
    const int b  = blockIdx.z;

#pragma unroll
    for (int p = 0; p < 4; p++) {
        int tl = (tid >> 4) + p * 16;
        int d4 = (tid & 15) * 4;
        float4 v = *(const float4*)&g_qkv[((size_t)(b * T_ + t0 + tl) * 1024)
                                          + 768 + kv * 64 + d4];
        vs[tl][d4 + 0] = v.x;
        vs[tl][d4 + 1] = v.y;
        vs[tl][d4 + 2] = v.z;
        vs[tl][d4 + 3] = v.w;
    }
    __syncthreads();

    const int d = tid >> 2;
    const int ts = (tid & 3) * 16;
    size_t base = (((size_t)(b * NKV_ + kv) * HD_) + d) * T_ + t0 + ts;
#pragma unroll
    for (int i = 0; i < 16; i++) {
        float x = vs[ts + i][d];
        __nv_bfloat16 h = __float2bfloat16(x);
        g_vth[base + i] = h;
        g_vtl[base + i] = __float2bfloat16(x - __bfloat162float(h));
    }
}

// ---------------- tensor-core causal flash attention ----------------------
// block = 128 threads (4 warps). Q tile 64 rows (16/warp), KV tile 32.
#define KSTR 72   // Q/K smem row stride (bf16) — conflict-free frag loads
#define VSTR 40   // V^T smem row stride (bf16)

__global__ __launch_bounds__(128) void attn_kernel()
{
    __shared__ __nv_bfloat16 sQh[64 * KSTR], sQl[64 * KSTR];
    __shared__ __nv_bfloat16 sKh[32 * KSTR], sKl[32 * KSTR];
    __shared__ __nv_bfloat16 sVh[64 * VSTR], sVl[64 * VSTR];

    const int tid  = threadIdx.x;
    const int lane = tid & 31;
    const int wid  = tid >> 5;
    const int wq   = wid * 16;
    const int g    = lane >> 2;
    const int t2   = (lane & 3) * 2;

    const int q0 = (gridDim.x - 1 - blockIdx.x) * 64;  // heavy tiles first
    const int h  = blockIdx.y;
    const int b  = blockIdx.z;
    const int kvh = h >> 1;

    // load Q tile (both splits)
    {
        const __nv_bfloat16* qbh = g_qh + (((size_t)b * NH_ + h) * T_ + q0) * HD_;
        const __nv_bfloat16* qbl = g_ql + (((size_t)b * NH_ + h) * T_ + q0) * HD_;
#pragma unroll
        for (int p = 0; p < 4; p++) {
            int i = tid + p * 128;          // 0..511 uint4
            int row = i >> 3, c = i & 7;
            *(uint4*)(sQh + row * KSTR + c * 8) = ((const uint4*)qbh)[i];
            *(uint4*)(sQl + row * KSTR + c * 8) = ((const uint4*)qbl)[i];
        }
    }
    __syncthreads();

    const int row0 = q0 + wq + g;
    const int row1 = row0 + 8;

    float m0 = -1e30f, m1 = -1e30f, l0 = 0.f, l1 = 0.f;
    float O[8][4];
#pragma unroll
    for (int n = 0; n < 8; n++)
#pragma unroll
        for (int q = 0; q < 4; q++) O[n][q] = 0.f;

    const __nv_bfloat16* kbh = g_kh + (((size_t)b * NKV_ + kvh) * T_) * HD_;
    const __nv_bfloat16* kbl = g_kl + (((size_t)b * NKV_ + kvh) * T_) * HD_;
    const __nv_bfloat16* vbh = g_vth + (((size_t)b * NKV_ + kvh) * HD_) * T_;
    const __nv_bfloat16* vbl = g_vtl + (((size_t)b * NKV_ + kvh) * HD_) * T_;

    const int nkt = q0 / 32 + 2;

    for (int kt = 0; kt < nkt; kt++) {
        const int kv0 = kt * 32;
        // load K tile [32][64] and V^T tile [64][32]
#pragma unroll
        for (int p = 0; p < 2; p++) {
            int i = tid + p * 128;              // 0..255
            int kr = i >> 3, kc = i & 7;        // K: 32 rows x 8 u4
            *(uint4*)(sKh + kr * KSTR + kc * 8) =
                *(const uint4*)(kbh + (size_t)(kv0 + kr) * HD_ + kc * 8);
            *(uint4*)(sKl + kr * KSTR + kc * 8) =
                *(const uint4*)(kbl + (size_t)(kv0 + kr) * HD_ + kc * 8);
            int vr = i >> 2, vc = i & 3;        // V: 64 rows x 4 u4
            *(uint4*)(sVh + vr * VSTR + vc * 8) =
                *(const uint4*)(vbh + (size_t)vr * T_ + kv0 + vc * 8);
            *(uint4*)(sVl + vr * VSTR + vc * 8) =
                *(const uint4*)(vbl + (size_t)vr * T_ + kv0 + vc * 8);
        }
        __syncthreads();

        // S = Q K^T (3-term split)
        float S[4][4];
#pragma unroll
        for (int n = 0; n < 4; n++)
#pragma unroll
            for (int q = 0; q < 4; q++) S[n][q] = 0.f;

#pragma unroll
        for (int ktile = 0; ktile < 4; ktile++) {
            const int kc = ktile * 16 + t2;
            u32 ah[4], al[4];
            ah[0] = *(const u32*)(sQh + (wq + g) * KSTR + kc);
            ah[1] = *(const u32*)(sQh + (wq + g + 8) * KSTR + kc);
            ah[2] = *(const u32*)(sQh + (wq + g) * KSTR + kc + 8);
            ah[3] = *(const u32*)(sQh + (wq + g + 8) * KSTR + kc + 8);
            al[0] = *(const u32*)(sQl + (wq + g) * KSTR + kc);
            al[1] = *(const u32*)(sQl + (wq + g + 8) * KSTR + kc);
            al[2] = *(const u32*)(sQl + (wq + g) * KSTR + kc + 8);
            al[3] = *(const u32*)(sQl + (wq + g + 8) * KSTR + kc + 8);
#pragma unroll
            for (int nt = 0; nt < 4; nt++) {
                u32 bh0 = *(const u32*)(sKh + (nt * 8 + g) * KSTR + kc);
                u32 bh1 = *(const u32*)(sKh + (nt * 8 + g) * KSTR + kc + 8);
                u32 bl0 = *(const u32*)(sKl + (nt * 8 + g) * KSTR + kc);
                u32 bl1 = *(const u32*)(sKl + (nt * 8 + g) * KSTR + kc + 8);
                mma_bf16(S[nt], ah, bh0, bh1);
                mma_bf16(S[nt], ah, bl0, bl1);
                mma_bf16(S[nt], al, bh0, bh1);
            }
        }

        // causal mask (only near diagonal)
        if (kv0 + 31 > row0) {
#pragma unroll
            for (int nt = 0; nt < 4; nt++) {
                int j0 = kv0 + nt * 8 + t2;
                if (j0 > row0)     S[nt][0] = -INFINITY;
                if (j0 + 1 > row0) S[nt][1] = -INFINITY;
                if (j0 > row1)     S[nt][2] = -INFINITY;
                if (j0 + 1 > row1) S[nt][3] = -INFINITY;
            }
        }

        // online softmax
        float t0m = -INFINITY, t1m = -INFINITY;
#pragma unroll
        for (int nt = 0; nt < 4; nt++) {
            t0m = fmaxf(t0m, fmaxf(S[nt][0], S[nt][1]));
            t1m = fmaxf(t1m, fmaxf(S[nt][2], S[nt][3]));
        }
        t0m = fmaxf(t0m, __shfl_xor_sync(0xffffffffu, t0m, 1));
        t0m = fmaxf(t0m, __shfl_xor_sync(0xffffffffu, t0m, 2));
        t1m = fmaxf(t1m, __shfl_xor_sync(0xffffffffu, t1m, 1));
        t1m = fmaxf(t1m, __shfl_xor_sync(0xffffffffu, t1m, 2));

        float mn0 = fmaxf(m0, t0m);
        float mn1 = fmaxf(m1, t1m);
        float c0 = __expf(m0 - mn0);
        float c1 = __expf(m1 - mn1);
        m0 = mn0; m1 = mn1;

        float ps0 = 0.f, ps1 = 0.f;
#pragma unroll
        for (int nt = 0; nt < 4; nt++) {
            S[nt][0] = __expf(S[nt][0] - mn0);
            S[nt][1] = __expf(S[nt][1] - mn0);
            S[nt][2] = __expf(S[nt][2] - mn1);
            S[nt][3] = __expf(S[nt][3] - mn1);
            ps0 += S[nt][0] + S[nt][1];
            ps1 += S[nt][2] + S[nt][3];
        }
        ps0 += __shfl_xor_sync(0xffffffffu, ps0, 1);
        ps0 += __shfl_xor_sync(0xffffffffu, ps0, 2);
        ps1 += __shfl_xor_sync(0xffffffffu, ps1, 1);
        ps1 += __shfl_xor_sync(0xffffffffu, ps1, 2);
        l0 = l0 * c0 + ps0;
        l1 = l1 * c1 + ps1;

#pragma unroll
        for (int n = 0; n < 8; n++) {
            O[n][0] *= c0; O[n][1] *= c0;
            O[n][2] *= c1; O[n][3] *= c1;
        }

        // P V (split P in-register)
#pragma unroll
        for (int kt2 = 0; kt2 < 2; kt2++) {
            u32 ph[4], pl[4];
#pragma unroll
            for (int half = 0; half < 2; half++) {
                float* sA = S[kt2 * 2 + half];
                u32 h01 = cvt2bf(sA[0], sA[1]);
                u32 h23 = cvt2bf(sA[2], sA[3]);
                float f0 = __uint_as_float(h01 << 16);
                float f1 = __uint_as_float(h01 & 0xffff0000u);
                float f2 = __uint_as_float(h23 << 16);
                float f3 = __uint_as_float(h23 & 0xffff0000u);
                ph[half * 2 + 0] = h01;      // a0/a2: row g
                ph[half * 2 + 1] = h23;      // a1/a3: row g+8
                pl[half * 2 + 0] = cvt2bf(sA[0] - f0, sA[1] - f1);
                pl[half * 2 + 1] = cvt2bf(sA[2] - f2, sA[3] - f3);
            }
            // reorder to a-layout: a0=k lo row g, a1=k lo row g+8, a2=k hi row g, a3=k hi row g+8
            u32 ahf[4] = {ph[0], ph[1], ph[2], ph[3]};
            u32 alf[4] = {pl[0], pl[1], pl[2], pl[3]};
            const int kc = kt2 * 16 + t2;
#pragma unroll
            for (int nd = 0; nd < 8; nd++) {
                u32 bh0 = *(const u32*)(sVh + (nd * 8 + g) * VSTR + kc);
                u32 bh1 = *(const u32*)(sVh + (nd * 8 + g) * VSTR + kc + 8);
                u32 bl0 = *(const u32*)(sVl + (nd * 8 + g) * VSTR + kc);
                u32 bl1 = *(const u32*)(sVl + (nd * 8 + g) * VSTR + kc + 8);
                mma_bf16(O[nd], ahf, bh0, bh1);
                mma_bf16(O[nd], alf, bh0, bh1);
                mma_bf16(O[nd], ahf, bl0, bl1);
            }
        }
        __syncthreads();
    }

    // epilogue
    float il0 = 1.f / l0;
    float il1 = 1.f / l1;
    float* y0 = g_y + ((size_t)b * T_ + row0) * DIM_ + h * HD_;
    float* y1 = g_y + ((size_t)b * T_ + row1) * DIM_ + h * HD_;
#pragma unroll
    for (int nd = 0; nd < 8; nd++) {
        int col = nd * 8 + t2;
        *(float2*)(y0 + col) = make_float2(O[nd][0] * il0, O[nd][1] * il0);
        *(float2*)(y1 + col) = make_float2(O[nd][2] * il1, O[nd][3] * il1);
    }
}

// ---------------- launch ---------------------------------------------------
extern "C" void kernel_launch(void* const* d_in, const int* in_sizes, int n_in,
                              void* d_out, int out_size)
{
    const float* x  = (const float*)d_in[0];
    const float* Wq = (const float*)d_in[1];
    const float* Wk = (const float*)d_in[2];
    const float* Wv = (const float*)d_in[3];
    const float* Wp = (const float*)d_in[4];
    float* out = (float*)d_out;

    float* qkv;  cudaGetSymbolAddress((void**)&qkv, g_qkv);
    float* ybuf; cudaGetSymbolAddress((void**)&ybuf, g_y);
    __nv_bfloat16 *xh, *xl, *yh, *yl, *wh, *wl;
    cudaGetSymbolAddress((void**)&xh, g_xh);
    cudaGetSymbolAddress((void**)&xl, g_xl);
    cudaGetSymbolAddress((void**)&yh, g_yh);
    cudaGetSymbolAddress((void**)&yl, g_yl);
    cudaGetSymbolAddress((void**)&wh, g_wh);
    cudaGetSymbolAddress((void**)&wl, g_wl);

    const int M = B_ * T_;  // 16384

    // split inputs/weights into bf16 hi/lo
    split_kernel<<<(M * DIM_) / 256, 256>>>(x, xh, xl);
    split_kernel<<<(512 * 512) / 256, 256>>>(Wq, wh, wl);
    split_kernel<<<(256 * 512) / 256, 256>>>(Wk, wh + (size_t)512 * 512,
                                             wl + (size_t)512 * 512);
    split_kernel<<<(256 * 512) / 256, 256>>>(Wv, wh + (size_t)768 * 512,
                                             wl + (size_t)768 * 512);
    split_kernel<<<(512 * 512) / 256, 256>>>(Wp, wh + (size_t)1024 * 512,
                                             wl + (size_t)1024 * 512);

    // fused QKV projection
    gemm_bf16_kernel<<<dim3(M / 128, 8), 256>>>(xh, xl, 0, qkv, 1024, 0);

    // RMSNorm + RoPE -> split bf16 Q/K; V transpose+split
    rope_kernel<<<M, 256>>>();
    vtrans_kernel<<<dim3(T_ / 64, NKV_, B_), 256>>>();

    // tensor-core flash attention
    attn_kernel<<<dim3(T_ / 64, NH_, B_), 128>>>();

    // output projection
    split_kernel<<<(M * DIM_) / 256, 256>>>(ybuf, yh, yl);
    gemm_bf16_kernel<<<dim3(M / 128, 4), 256>>>(yh, yl, 1024, out, 512, 0);
}

// round 5
// speedup vs baseline: 2.7427x; 1.1018x over previous
#include <cuda_runtime.h>
#include <cuda_bf16.h>
#include <math.h>
#include <stdint.h>

// Problem constants
#define B_   8
#define T_   2048
#define DIM_ 512
#define NH_  8
#define NKV_ 4
#define HD_  64
#define EPS_ 1.1920928955078125e-07f
#define FREQ_C 0.41524101186091903f   // log2(10000)/32

typedef unsigned long long u64;
typedef uint32_t u32;

// ---------------- scratch (device globals; no allocation allowed) ----------
__device__ float g_qkv[(size_t)B_ * T_ * 1024];        // raw q|k|v projections
__device__ float g_y[(size_t)B_ * T_ * DIM_];          // attention output

// bf16 split operands for projections
__device__ __nv_bfloat16 g_xh[(size_t)B_ * T_ * DIM_];
__device__ __nv_bfloat16 g_xl[(size_t)B_ * T_ * DIM_];
__device__ __nv_bfloat16 g_yh[(size_t)B_ * T_ * DIM_];
__device__ __nv_bfloat16 g_yl[(size_t)B_ * T_ * DIM_];
__device__ __nv_bfloat16 g_wh[(size_t)1536 * DIM_];
__device__ __nv_bfloat16 g_wl[(size_t)1536 * DIM_];

// bf16 split attention operands
__device__ __nv_bfloat16 g_qh[(size_t)B_ * NH_ * T_ * HD_];   // [b][h][t][d], scaled 1/8
__device__ __nv_bfloat16 g_ql[(size_t)B_ * NH_ * T_ * HD_];
__device__ __nv_bfloat16 g_kh[(size_t)B_ * NKV_ * T_ * HD_];  // [b][kv][t][d]
__device__ __nv_bfloat16 g_kl[(size_t)B_ * NKV_ * T_ * HD_];
__device__ __nv_bfloat16 g_vth[(size_t)B_ * NKV_ * HD_ * T_]; // [b][kv][d][t]
__device__ __nv_bfloat16 g_vtl[(size_t)B_ * NKV_ * HD_ * T_];

// ---------------- small helpers -------------------------------------------
__device__ __forceinline__ u32 cvt2bf(float lo, float hi) {
    u32 r;
    asm("cvt.rn.bf16x2.f32 %0, %1, %2;" : "=r"(r) : "f"(hi), "f"(lo));
    return r;
}

__device__ __forceinline__ void mma_bf16(float* c, const u32* a, u32 b0, u32 b1) {
    asm volatile(
        "mma.sync.aligned.m16n8k16.row.col.f32.bf16.bf16.f32 "
        "{%0,%1,%2,%3}, {%4,%5,%6,%7}, {%8,%9}, {%0,%1,%2,%3};\n"
        : "+f"(c[0]), "+f"(c[1]), "+f"(c[2]), "+f"(c[3])
        : "r"(a[0]), "r"(a[1]), "r"(a[2]), "r"(a[3]), "r"(b0), "r"(b1));
}

__device__ __forceinline__ u32 s2u(const void* p) {
    return (u32)__cvta_generic_to_shared(p);
}

__device__ __forceinline__ void ldsm4(u32* r, u32 addr) {
    asm volatile(
        "ldmatrix.sync.aligned.m8n8.x4.shared.b16 {%0,%1,%2,%3}, [%4];"
        : "=r"(r[0]), "=r"(r[1]), "=r"(r[2]), "=r"(r[3]) : "r"(addr));
}

// ---------------- split fp32 -> bf16 hi/lo --------------------------------
__global__ __launch_bounds__(256) void split_kernel(
    const float* __restrict__ src, __nv_bfloat16* __restrict__ h,
    __nv_bfloat16* __restrict__ l)
{
    int i = blockIdx.x * 256 + threadIdx.x;
    float x = src[i];
    __nv_bfloat16 hh = __float2bfloat16(x);
    float r = x - __bfloat162float(hh);
    h[i] = hh;
    l[i] = __float2bfloat16(r);
}

// ---------------- bf16-split tensor-core GEMM (ldmatrix) ------------------
#define LDSB 40

__global__ __launch_bounds__(256) void gemm_bf16_kernel(
    const __nv_bfloat16* __restrict__ Ah, const __nv_bfloat16* __restrict__ Al,
    int wrow0, float* __restrict__ C, int ldc, int coff)
{
    __shared__ __nv_bfloat16 sAh[128 * LDSB];
    __shared__ __nv_bfloat16 sAl[128 * LDSB];
    __shared__ __nv_bfloat16 sWh[128 * LDSB];
    __shared__ __nv_bfloat16 sWl[128 * LDSB];

    const int tid  = threadIdx.x;
    const int m0   = blockIdx.x * 128;
    const int n0   = blockIdx.y * 128;
    const int lane = tid & 31;
    const int wid  = tid >> 5;
    const int wm   = (wid >> 2) * 64;
    const int wn   = (wid & 3) * 32;
    const int g    = lane >> 2;
    const int t2   = (lane & 3) * 2;

    // ldmatrix lane-address components
    const int arow = lane & 15;            // A: row within 16
    const int ac8  = (lane >> 4) * 8;      // A: k-subcolumn
    const int brow = ((lane >> 4) * 8) + (lane & 7);  // B: row within 16 (nt pair)
    const int bc8  = ((lane >> 3) & 1) * 8;           // B: k-subcolumn

    const u32 aAh = s2u(sAh), aAl = s2u(sAl);
    const u32 aWh = s2u(sWh), aWl = s2u(sWl);

    const __nv_bfloat16* Wh = g_wh + (size_t)wrow0 * 512;
    const __nv_bfloat16* Wl = g_wl + (size_t)wrow0 * 512;

    float acc[4][4][4];
#pragma unroll
    for (int i = 0; i < 4; i++)
#pragma unroll
        for (int j = 0; j < 4; j++)
#pragma unroll
            for (int q = 0; q < 4; q++) acc[i][j][q] = 0.f;

    const int l_row0 = tid >> 2;
    const int l_c4   = tid & 3;

    uint4 pAh[2], pAl[2], pWh[2], pWl[2];
#pragma unroll
    for (int p = 0; p < 2; p++) {
        int row = l_row0 + p * 64;
        size_t ao = (size_t)(m0 + row) * 512 + l_c4 * 8;
        size_t wo = (size_t)(n0 + row) * 512 + l_c4 * 8;
        pAh[p] = *(const uint4*)(Ah + ao);
        pAl[p] = *(const uint4*)(Al + ao);
        pWh[p] = *(const uint4*)(Wh + wo);
        pWl[p] = *(const uint4*)(Wl + wo);
    }

    for (int it = 0; it < 16; it++) {
#pragma unroll
        for (int p = 0; p < 2; p++) {
            int row = l_row0 + p * 64;
            int so = row * LDSB + l_c4 * 8;
            *(uint4*)(sAh + so) = pAh[p];
            *(uint4*)(sAl + so) = pAl[p];
            *(uint4*)(sWh + so) = pWh[p];
            *(uint4*)(sWl + so) = pWl[p];
        }
        __syncthreads();

        if (it < 15) {
            int k0 = (it + 1) * 32;
#pragma unroll
            for (int p = 0; p < 2; p++) {
                int row = l_row0 + p * 64;
                size_t ao = (size_t)(m0 + row) * 512 + k0 + l_c4 * 8;
                size_t wo = (size_t)(n0 + row) * 512 + k0 + l_c4 * 8;
                pAh[p] = *(const uint4*)(Ah + ao);
                pAl[p] = *(const uint4*)(Al + ao);
                pWh[p] = *(const uint4*)(Wh + wo);
                pWl[p] = *(const uint4*)(Wl + wo);
            }
        }

#pragma unroll
        for (int ks = 0; ks < 32; ks += 16) {
            u32 ah[4][4], al[4][4];
#pragma unroll
            for (int mt = 0; mt < 4; mt++) {
                u32 off = (u32)(((wm + mt * 16 + arow) * LDSB + ks + ac8) * 2);
                ldsm4(ah[mt], aAh + off);
                ldsm4(al[mt], aAl + off);
            }
            u32 bh[8], bl[8];   // [nt*2 + (b0/b1)]
#pragma unroll
            for (int p = 0; p < 2; p++) {
                u32 off = (u32)(((wn + p * 16 + brow) * LDSB + ks + bc8) * 2);
                ldsm4(bh + p * 4, aWh + off);
                ldsm4(bl + p * 4, aWl + off);
            }
#pragma unroll
            for (int nt = 0; nt < 4; nt++) {
                u32 bh0 = bh[nt * 2], bh1 = bh[nt * 2 + 1];
                u32 bl0 = bl[nt * 2], bl1 = bl[nt * 2 + 1];
#pragma unroll
                for (int mt = 0; mt < 4; mt++) {
                    mma_bf16(acc[mt][nt], ah[mt], bh0, bh1);
                    mma_bf16(acc[mt][nt], ah[mt], bl0, bl1);
                    mma_bf16(acc[mt][nt], al[mt], bh0, bh1);
                }
            }
        }
        __syncthreads();
    }

#pragma unroll
    for (int mt = 0; mt < 4; mt++) {
#pragma unroll
        for (int nt = 0; nt < 4; nt++) {
            int row = m0 + wm + mt * 16 + g;
            int col = coff + n0 + wn + nt * 8 + t2;
            float* c = acc[mt][nt];
            *(float2*)&C[(size_t)row * ldc + col] = make_float2(c[0], c[1]);
            *(float2*)&C[(size_t)(row + 8) * ldc + col] = make_float2(c[2], c[3]);
        }
    }
}

// ---------------- RMSNorm + RoPE -> split bf16 Q/K ------------------------
__device__ __forceinline__ void norm_rope_split(
    const float* __restrict__ src, __nv_bfloat16* __restrict__ dh,
    __nv_bfloat16* __restrict__ dl, int lane, float cv, float sv, float scale)
{
    float x1 = src[lane];
    float x2 = src[lane + 32];
    float ss = x1 * x1 + x2 * x2;
#pragma unroll
    for (int off = 16; off > 0; off >>= 1)
        ss += __shfl_xor_sync(0xffffffffu, ss, off);
    float ir = rsqrtf(ss * (1.f / 64.f) + EPS_) * scale;
    x1 *= ir;
    x2 *= ir;
    float o1 = x1 * cv + x2 * sv;
    float o2 = x2 * cv - x1 * sv;
    __nv_bfloat16 h1 = __float2bfloat16(o1);
    __nv_bfloat16 h2 = __float2bfloat16(o2);
    dh[lane]      = h1;
    dh[lane + 32] = h2;
    dl[lane]      = __float2bfloat16(o1 - __bfloat162float(h1));
    dl[lane + 32] = __float2bfloat16(o2 - __bfloat162float(h2));
}

__global__ __launch_bounds__(256) void rope_kernel()
{
    const int tok = blockIdx.x;
    const int b = tok >> 11;
    const int t = tok & (T_ - 1);
    const int lane = threadIdx.x & 31;
    const int w = threadIdx.x >> 5;

    const float* row = g_qkv + (size_t)tok * 1024;

    float inv_freq = exp2f(-(float)lane * FREQ_C);
    float f = (float)t * inv_freq;
    float sv, cv;
    sincosf(f, &sv, &cv);

    size_t qo = (((size_t)b * NH_ + w) * T_ + t) * HD_;
    norm_rope_split(row + w * 64, g_qh + qo, g_ql + qo, lane, cv, sv, 0.125f);
    if (w < 4) {
        size_t ko = (((size_t)b * NKV_ + w) * T_ + t) * HD_;
        norm_rope_split(row + 512 + w * 64, g_kh + ko, g_kl + ko,
                        lane, cv, sv, 1.0f);
    }
}

// ---------------- V transpose + split: g_qkv -> [b][kv][d][t] bf16 --------
__global__ __launch_bounds__(256) void vtrans_kernel()
{
    __shared__ float vs[64][65];
    const int tid = threadIdx.x;
    const int t0 = blockIdx.x * 64;
    const int kv = blockIdx.y;
    const int b  = blockIdx.z;

#pragma unroll
    for (int p = 0; p < 4; p++) {
        int tl = (tid >> 4) + p * 16;
        int d4 = (tid & 15) * 4;
        float4 v = *(const float4*)&g_qkv[((size_t)(b * T_ + t0 + tl) * 1024)
                                          + 768 + kv * 64 + d4];
        vs[tl][d4 + 0] = v.x;
        vs[tl][d4 + 1] = v.y;
        vs[tl][d4 + 2] = v.z;
        vs[tl][d4 + 3] = v.w;
    }
    __syncthreads();

    const int d = tid >> 2;
    const int ts = (tid & 3) * 16;
    size_t base = (((size_t)(b * NKV_ + kv) * HD_) + d) * T_ + t0 + ts;
#pragma unroll
    for (int i = 0; i < 16; i++) {
        float x = vs[ts + i][d];
        __nv_bfloat16 h = __float2bfloat16(x);
        g_vth[base + i] = h;
        g_vtl[base + i] = __float2bfloat16(x - __bfloat162float(h));
    }
}

// ---------------- tensor-core causal flash attention ----------------------
// 128 threads (4 warps). Q tile 64 rows (16/warp), KV tile 32.
// Q fragments register-resident; all smem frag loads via ldmatrix.
#define KSTR 72
#define VSTR 40

__global__ __launch_bounds__(128) void attn_kernel()
{
    __shared__ __nv_bfloat16 sQh[64 * KSTR], sQl[64 * KSTR];
    __shared__ __nv_bfloat16 sKh[32 * KSTR], sKl[32 * KSTR];
    __shared__ __nv_bfloat16 sVh[64 * VSTR], sVl[64 * VSTR];

    const int tid  = threadIdx.x;
    const int lane = tid & 31;
    const int wid  = tid >> 5;
    const int wq   = wid * 16;
    const int g    = lane >> 2;
    const int t2   = (lane & 3) * 2;

    const int arow = lane & 15;
    const int ac8  = (lane >> 4) * 8;
    const int brow = ((lane >> 4) * 8) + (lane & 7);
    const int bc8  = ((lane >> 3) & 1) * 8;

    const int q0 = (gridDim.x - 1 - blockIdx.x) * 64;  // heavy tiles first
    const int h  = blockIdx.y;
    const int b  = blockIdx.z;
    const int kvh = h >> 1;

    // load Q tile into smem
    {
        const __nv_bfloat16* qbh = g_qh + (((size_t)b * NH_ + h) * T_ + q0) * HD_;
        const __nv_bfloat16* qbl = g_ql + (((size_t)b * NH_ + h) * T_ + q0) * HD_;
#pragma unroll
        for (int p = 0; p < 4; p++) {
            int i = tid + p * 128;
            int row = i >> 3, c = i & 7;
            *(uint4*)(sQh + row * KSTR + c * 8) = ((const uint4*)qbh)[i];
            *(uint4*)(sQl + row * KSTR + c * 8) = ((const uint4*)qbl)[i];
        }
    }
    __syncthreads();

    // hoist Q fragments into registers (all 4 k-chunks, hi+lo)
    u32 qfh[4][4], qfl[4][4];
    {
        const u32 aQh = s2u(sQh), aQl = s2u(sQl);
#pragma unroll
        for (int ktile = 0; ktile < 4; ktile++) {
            u32 off = (u32)(((wq + arow) * KSTR + ktile * 16 + ac8) * 2);
            ldsm4(qfh[ktile], aQh + off);
            ldsm4(qfl[ktile], aQl + off);
        }
    }

    const int row0 = q0 + wq + g;
    const int row1 = row0 + 8;

    float m0 = -1e30f, m1 = -1e30f, l0 = 0.f, l1 = 0.f;
    float O[8][4];
#pragma unroll
    for (int n = 0; n < 8; n++)
#pragma unroll
        for (int q = 0; q < 4; q++) O[n][q] = 0.f;

    const __nv_bfloat16* kbh = g_kh + (((size_t)b * NKV_ + kvh) * T_) * HD_;
    const __nv_bfloat16* kbl = g_kl + (((size_t)b * NKV_ + kvh) * T_) * HD_;
    const __nv_bfloat16* vbh = g_vth + (((size_t)b * NKV_ + kvh) * HD_) * T_;
    const __nv_bfloat16* vbl = g_vtl + (((size_t)b * NKV_ + kvh) * HD_) * T_;

    const u32 aKh = s2u(sKh), aKl = s2u(sKl);
    const u32 aVh = s2u(sVh), aVl = s2u(sVl);

    const int nkt = q0 / 32 + 2;

    for (int kt = 0; kt < nkt; kt++) {
        const int kv0 = kt * 32;
#pragma unroll
        for (int p = 0; p < 2; p++) {
            int i = tid + p * 128;
            int kr = i >> 3, kc = i & 7;
            *(uint4*)(sKh + kr * KSTR + kc * 8) =
                *(const uint4*)(kbh + (size_t)(kv0 + kr) * HD_ + kc * 8);
            *(uint4*)(sKl + kr * KSTR + kc * 8) =
                *(const uint4*)(kbl + (size_t)(kv0 + kr) * HD_ + kc * 8);
            int vr = i >> 2, vc = i & 3;
            *(uint4*)(sVh + vr * VSTR + vc * 8) =
                *(const uint4*)(vbh + (size_t)vr * T_ + kv0 + vc * 8);
            *(uint4*)(sVl + vr * VSTR + vc * 8) =
                *(const uint4*)(vbl + (size_t)vr * T_ + kv0 + vc * 8);
        }
        __syncthreads();

        // S = Q K^T (3-term split)
        float S[4][4];
#pragma unroll
        for (int n = 0; n < 4; n++)
#pragma unroll
            for (int q = 0; q < 4; q++) S[n][q] = 0.f;

#pragma unroll
        for (int ktile = 0; ktile < 4; ktile++) {
            u32 kh[8], kl[8];   // [nt*2 + b-reg]
#pragma unroll
            for (int p = 0; p < 2; p++) {
                u32 off = (u32)(((p * 16 + brow) * KSTR + ktile * 16 + bc8) * 2);
                ldsm4(kh + p * 4, aKh + off);
                ldsm4(kl + p * 4, aKl + off);
            }
#pragma unroll
            for (int nt = 0; nt < 4; nt++) {
                mma_bf16(S[nt], qfh[ktile], kh[nt * 2], kh[nt * 2 + 1]);
                mma_bf16(S[nt], qfh[ktile], kl[nt * 2], kl[nt * 2 + 1]);
                mma_bf16(S[nt], qfl[ktile], kh[nt * 2], kh[nt * 2 + 1]);
            }
        }

        // causal mask (only near diagonal)
        if (kv0 + 31 > row0) {
#pragma unroll
            for (int nt = 0; nt < 4; nt++) {
                int j0 = kv0 + nt * 8 + t2;
                if (j0 > row0)     S[nt][0] = -INFINITY;
                if (j0 + 1 > row0) S[nt][1] = -INFINITY;
                if (j0 > row1)     S[nt][2] = -INFINITY;
                if (j0 + 1 > row1) S[nt][3] = -INFINITY;
            }
        }

        // online softmax
        float t0m = -INFINITY, t1m = -INFINITY;
#pragma unroll
        for (int nt = 0; nt < 4; nt++) {
            t0m = fmaxf(t0m, fmaxf(S[nt][0], S[nt][1]));
            t1m = fmaxf(t1m, fmaxf(S[nt][2], S[nt][3]));
        }
        t0m = fmaxf(t0m, __shfl_xor_sync(0xffffffffu, t0m, 1));
        t0m = fmaxf(t0m, __shfl_xor_sync(0xffffffffu, t0m, 2));
        t1m = fmaxf(t1m, __shfl_xor_sync(0xffffffffu, t1m, 1));
        t1m = fmaxf(t1m, __shfl_xor_sync(0xffffffffu, t1m, 2));

        float mn0 = fmaxf(m0, t0m);
        float mn1 = fmaxf(m1, t1m);
        float c0 = __expf(m0 - mn0);
        float c1 = __expf(m1 - mn1);
        m0 = mn0; m1 = mn1;

        float ps0 = 0.f, ps1 = 0.f;
#pragma unroll
        for (int nt = 0; nt < 4; nt++) {
            S[nt][0] = __expf(S[nt][0] - mn0);
            S[nt][1] = __expf(S[nt][1] - mn0);
            S[nt][2] = __expf(S[nt][2] - mn1);
            S[nt][3] = __expf(S[nt][3] - mn1);
            ps0 += S[nt][0] + S[nt][1];
            ps1 += S[nt][2] + S[nt][3];
        }
        ps0 += __shfl_xor_sync(0xffffffffu, ps0, 1);
        ps0 += __shfl_xor_sync(0xffffffffu, ps0, 2);
        ps1 += __shfl_xor_sync(0xffffffffu, ps1, 1);
        ps1 += __shfl_xor_sync(0xffffffffu, ps1, 2);
        l0 = l0 * c0 + ps0;
        l1 = l1 * c1 + ps1;

#pragma unroll
        for (int n = 0; n < 8; n++) {
            O[n][0] *= c0; O[n][1] *= c0;
            O[n][2] *= c1; O[n][3] *= c1;
        }

        // P V (split P in-register)
#pragma unroll
        for (int kt2 = 0; kt2 < 2; kt2++) {
            u32 ahf[4], alf[4];
#pragma unroll
            for (int half = 0; half < 2; half++) {
                float* sA = S[kt2 * 2 + half];
                u32 h01 = cvt2bf(sA[0], sA[1]);
                u32 h23 = cvt2bf(sA[2], sA[3]);
                float f0 = __uint_as_float(h01 << 16);
                float f1 = __uint_as_float(h01 & 0xffff0000u);
                float f2 = __uint_as_float(h23 << 16);
                float f3 = __uint_as_float(h23 & 0xffff0000u);
                ahf[half * 2 + 0] = h01;
                ahf[half * 2 + 1] = h23;
                alf[half * 2 + 0] = cvt2bf(sA[0] - f0, sA[1] - f1);
                alf[half * 2 + 1] = cvt2bf(sA[2] - f2, sA[3] - f3);
            }
            const int kc = kt2 * 16;
#pragma unroll
            for (int p = 0; p < 4; p++) {   // nd pairs
                u32 vh[4], vl[4];
                u32 off = (u32)(((p * 16 + brow) * VSTR + kc + bc8) * 2);
                ldsm4(vh, aVh + off);
                ldsm4(vl, aVl + off);
                mma_bf16(O[p * 2 + 0], ahf, vh[0], vh[1]);
                mma_bf16(O[p * 2 + 0], alf, vh[0], vh[1]);
                mma_bf16(O[p * 2 + 0], ahf, vl[0], vl[1]);
                mma_bf16(O[p * 2 + 1], ahf, vh[2], vh[3]);
                mma_bf16(O[p * 2 + 1], alf, vh[2], vh[3]);
                mma_bf16(O[p * 2 + 1], ahf, vl[2], vl[3]);
            }
        }
        __syncthreads();
    }

    // epilogue
    float il0 = 1.f / l0;
    float il1 = 1.f / l1;
    float* y0 = g_y + ((size_t)b * T_ + row0) * DIM_ + h * HD_;
    float* y1 = g_y + ((size_t)b * T_ + row1) * DIM_ + h * HD_;
#pragma unroll
    for (int nd = 0; nd < 8; nd++) {
        int col = nd * 8 + t2;
        *(float2*)(y0 + col) = make_float2(O[nd][0] * il0, O[nd][1] * il0);
        *(float2*)(y1 + col) = make_float2(O[nd][2] * il1, O[nd][3] * il1);
    }
}

// ---------------- launch ---------------------------------------------------
extern "C" void kernel_launch(void* const* d_in, const int* in_sizes, int n_in,
                              void* d_out, int out_size)
{
    const float* x  = (const float*)d_in[0];
    const float* Wq = (const float*)d_in[1];
    const float* Wk = (const float*)d_in[2];
    const float* Wv = (const float*)d_in[3];
    const float* Wp = (const float*)d_in[4];
    float* out = (float*)d_out;

    float* qkv;  cudaGetSymbolAddress((void**)&qkv, g_qkv);
    float* ybuf; cudaGetSymbolAddress((void**)&ybuf, g_y);
    __nv_bfloat16 *xh, *xl, *yh, *yl, *wh, *wl;
    cudaGetSymbolAddress((void**)&xh, g_xh);
    cudaGetSymbolAddress((void**)&xl, g_xl);
    cudaGetSymbolAddress((void**)&yh, g_yh);
    cudaGetSymbolAddress((void**)&yl, g_yl);
    cudaGetSymbolAddress((void**)&wh, g_wh);
    cudaGetSymbolAddress((void**)&wl, g_wl);

    const int M = B_ * T_;  // 16384

    // split inputs/weights into bf16 hi/lo
    split_kernel<<<(M * DIM_) / 256, 256>>>(x, xh, xl);
    split_kernel<<<(512 * 512) / 256, 256>>>(Wq, wh, wl);
    split_kernel<<<(256 * 512) / 256, 256>>>(Wk, wh + (size_t)512 * 512,
                                             wl + (size_t)512 * 512);
    split_kernel<<<(256 * 512) / 256, 256>>>(Wv, wh + (size_t)768 * 512,
                                             wl + (size_t)768 * 512);
    split_kernel<<<(512 * 512) / 256, 256>>>(Wp, wh + (size_t)1024 * 512,
                                             wl + (size_t)1024 * 512);

    // fused QKV projection
    gemm_bf16_kernel<<<dim3(M / 128, 8), 256>>>(xh, xl, 0, qkv, 1024, 0);

    // RMSNorm + RoPE -> split bf16 Q/K; V transpose+split
    rope_kernel<<<M, 256>>>();
    vtrans_kernel<<<dim3(T_ / 64, NKV_, B_), 256>>>();

    // tensor-core flash attention
    attn_kernel<<<dim3(T_ / 64, NH_, B_), 128>>>();

    // output projection
    split_kernel<<<(M * DIM_) / 256, 256>>>(ybuf, yh, yl);
    gemm_bf16_kernel<<<dim3(M / 128, 4), 256>>>(yh, yl, 1024, out, 512, 0);
}